// round 16
// baseline (speedup 1.0000x reference)
#include <cuda_runtime.h>
#include <cuda_bf16.h>
#include <math.h>

#define NA 4096
#define NP 8192
#define NT 4096
#define NC 2048
typedef unsigned long long ull;

// ---------------- device scratch ----------------
__device__ float g_ha[NA*128];
__device__ float g_hp[NP*128];
__device__ float g_ht[NT*128];
__device__ float g_hc[NC*128];
__device__ float g_xt[NA*128];
__device__ __nv_bfloat16 g_anh[NA*128];
__device__ __nv_bfloat16 g_anl[NA*128];
__device__ __nv_bfloat16 g_snh[(NP+NT+NC)*128];
__device__ __nv_bfloat16 g_snl[(NP+NT+NC)*128];
__device__ __nv_bfloat16 g_hsT[(NP+NT+NC)*128];
__device__ float g_gp[NP*128];
__device__ float g_gt[NT*128];
__device__ float g_gc[NC*128];
__device__ float g_alsp[NP];
__device__ float g_alst[NT];
__device__ float g_alsc[NC];
__device__ float g_ald[3*NA];
__device__ float g_wdv[3*128];
__device__ unsigned g_mxsEnc[3];
__device__ float g_acc[3*NA*128];
__device__ float g_den[3*NA];
__device__ float g_ssum[4];
__device__ float g_alpha[4];
__device__ float g_agg1[NA*128];
__device__ float g_deg[NA];
__device__ float g_h1[NA*256];
__device__ float g_q[NA*64];
__device__ float g_aggq[NA*64];
__device__ __nv_bfloat16 g_wth[147456];
__device__ __nv_bfloat16 g_wtl[147456];

__device__ __forceinline__ unsigned enc_f(float f) {
    unsigned b = __float_as_uint(f);
    return (b & 0x80000000u) ? ~b : (b | 0x80000000u);
}
__device__ __forceinline__ float dec_f(unsigned u) {
    unsigned b = (u & 0x80000000u) ? (u ^ 0x80000000u) : ~u;
    return __uint_as_float(b);
}
__device__ __forceinline__ unsigned smem_u32(const void* p) {
    unsigned a;
    asm("{ .reg .u64 t; cvta.to.shared.u64 t, %1; cvt.u32.u64 %0, t; }" : "=r"(a) : "l"(p));
    return a;
}
__device__ __forceinline__ void fma2(ull& d, ull a, ull b) {
    asm("fma.rn.f32x2 %0, %1, %2, %0;" : "+l"(d) : "l"(a), "l"(b));
}
__device__ __forceinline__ ull packf2(float x, float y) {
    ull r; asm("mov.b64 %0, {%1, %2};" : "=l"(r) : "f"(x), "f"(y)); return r;
}
__device__ __forceinline__ float2 unpackf2(ull v) {
    float2 r; asm("mov.b64 {%0, %1}, %2;" : "=f"(r.x), "=f"(r.y) : "l"(v)); return r;
}
__device__ __forceinline__ void ldsm4(unsigned addr, unsigned& r0, unsigned& r1,
                                      unsigned& r2, unsigned& r3) {
    asm volatile("ldmatrix.sync.aligned.m8n8.x4.shared.b16 {%0,%1,%2,%3},[%4];"
                 : "=r"(r0), "=r"(r1), "=r"(r2), "=r"(r3) : "r"(addr));
}
__device__ __forceinline__ void mma_bf16(float* d, unsigned a0, unsigned a1,
                                         unsigned a2, unsigned a3,
                                         unsigned b0, unsigned b1) {
    asm volatile(
        "mma.sync.aligned.m16n8k16.row.col.f32.bf16.bf16.f32 "
        "{%0,%1,%2,%3},{%4,%5,%6,%7},{%8,%9},{%0,%1,%2,%3};"
        : "+f"(d[0]), "+f"(d[1]), "+f"(d[2]), "+f"(d[3])
        : "r"(a0), "r"(a1), "r"(a2), "r"(a3), "r"(b0), "r"(b1));
}
__device__ __forceinline__ unsigned pack_bf2(float a, float b) {
    __nv_bfloat16 x = __float2bfloat16(a), y = __float2bfloat16(b);
    return ((unsigned)__bfloat16_as_ushort(y) << 16) | __bfloat16_as_ushort(x);
}
__device__ __forceinline__ void cp16(unsigned dst, const void* src) {
    asm volatile("cp.async.cg.shared.global [%0], [%1], 16;" :: "r"(dst), "l"(src));
}
#define CP_WAIT() asm volatile("cp.async.commit_group;\ncp.async.wait_group 0;" ::: "memory")

// ---------------- fused zero init + wvec ----------------
__global__ void zero_wvec(float* __restrict__ acc, float* __restrict__ agg1,
                          float* __restrict__ aggq, float* __restrict__ den,
                          float* __restrict__ deg, float* __restrict__ ssum,
                          unsigned* __restrict__ mxsEnc,
                          const float* __restrict__ W3, const float* __restrict__ a3,
                          float* __restrict__ wdv) {
    if (blockIdx.x >= 9281) {
        int i = blockIdx.x - 9281, k = threadIdx.x;
        __shared__ float sa[128];
        if (k < 128) sa[k] = a3[i * 128 + k];
        __syncthreads();
        if (k < 128) {
            const float* W = W3 + (size_t)i * 16384 + (size_t)k * 128;
            float s = 0.f;
            #pragma unroll 8
            for (int c = 0; c < 128; c++) s += W[c] * sa[c];
            wdv[i * 128 + k] = s;
        }
        return;
    }
    int i = blockIdx.x * 256 + threadIdx.x;
    if (i < 1572864) { acc[i] = 0.f; return; }
    i -= 1572864; if (i < 524288) { agg1[i] = 0.f; return; }
    i -= 524288;  if (i < 262144) { aggq[i] = 0.f; return; }
    i -= 262144;  if (i < 12288)  { den[i] = 0.f; return; }
    i -= 12288;   if (i < 4096)   { deg[i] = 0.f; return; }
    i -= 4096;    if (i < 4)      { ssum[i] = 0.f; return; }
    i -= 4;       if (i < 3)      mxsEnc[i] = enc_f(-3.0e38f);
}

// ---------------- wprep ----------------
struct WJob { const float* W; int K, KP, N, off; };
struct WJobs { WJob j[8]; int total; };

__global__ void wprep(WJobs P, __nv_bfloat16* __restrict__ wth,
                      __nv_bfloat16* __restrict__ wtl) {
    int idx = blockIdx.x * 256 + threadIdx.x;
    if (idx >= P.total) return;
    int sel = 0;
    #pragma unroll
    for (int i = 1; i < 8; i++)
        if (idx >= P.j[i].off) sel = i;
    WJob J = P.j[sel];
    int local = idx - J.off;
    int n = local / J.KP, k = local - n * J.KP;
    float v = (k < J.K) ? J.W[(size_t)k * J.N + n] : 0.f;
    __nv_bfloat16 hi = __float2bfloat16(v);
    __nv_bfloat16 lo = __float2bfloat16(v - __bfloat162float(hi));
    wth[idx] = hi;
    wtl[idx] = lo;
}

// ---------------- fp32 SIMT linear, f32x2 inner ----------------
struct LJob { const float *A, *W, *bias; float* C; int K, blkStart; };
struct LJobs { LJob j[5]; int n; };

__global__ __launch_bounds__(256) void lin_f32(LJobs P) {
    __shared__ __align__(16) float As[16][64];
    __shared__ __align__(16) float Ws[16][128];
    int bid = blockIdx.x;
    int sel = 0;
    #pragma unroll
    for (int i = 1; i < 5; i++)
        if (i < P.n && bid >= P.j[i].blkStart) sel = i;
    LJob J = P.j[sel];
    int rb = (bid - J.blkStart) * 64;
    int K = J.K;
    int t = threadIdx.x, cg = t & 31, rg = t >> 5;
    ull acc2[8][2];
    #pragma unroll
    for (int i = 0; i < 8; i++) { acc2[i][0] = 0ull; acc2[i][1] = 0ull; }

    for (int k0 = 0; k0 < K; k0 += 16) {
        for (int i = t; i < 1024; i += 256) {
            int r = i >> 4, kk = i & 15, kg = k0 + kk;
            As[kk][r] = (kg < K) ? J.A[(size_t)(rb + r) * K + kg] : 0.f;
        }
        for (int i = t; i < 512; i += 256) {
            int kk = i >> 5, cq = i & 31, kg = k0 + kk;
            float4 w = (kg < K) ? *(const float4*)&J.W[(size_t)kg * 128 + cq * 4]
                                : make_float4(0.f, 0.f, 0.f, 0.f);
            *(float4*)&Ws[kk][cq * 4] = w;
        }
        __syncthreads();
        #pragma unroll
        for (int kk = 0; kk < 16; kk++) {
            ulonglong2 w2 = *(ulonglong2*)&Ws[kk][cg * 4];
            #pragma unroll
            for (int i = 0; i < 8; i++) {
                float a = As[kk][rg * 8 + i];
                ull ap = packf2(a, a);
                fma2(acc2[i][0], ap, w2.x);
                fma2(acc2[i][1], ap, w2.y);
            }
        }
        __syncthreads();
    }
    #pragma unroll
    for (int i = 0; i < 8; i++) {
        int row = rb + rg * 8 + i;
        float2 v01 = unpackf2(acc2[i][0]);
        float2 v23 = unpackf2(acc2[i][1]);
        int col = cg * 4;
        J.C[(size_t)row * 128 + col]     = v01.x + J.bias[col];
        J.C[(size_t)row * 128 + col + 1] = v01.y + J.bias[col + 1];
        J.C[(size_t)row * 128 + col + 2] = v23.x + J.bias[col + 2];
        J.C[(size_t)row * 128 + col + 3] = v23.y + J.bias[col + 3];
    }
}

// ---------------- batched HMMA linear (3-pass bf16 split) ----------------
struct MJob {
    const float *A, *A2, *bias, *addD, *degp, *degpA;
    float* C;
    int woff, woff2, M, K, K2, KP, KP2, N, relu, colBlks, blkStart;
};
struct MJobs { MJob j[5]; int n; };

#define LM_AH 0
#define LM_AL 9216
#define LM_BH 18432
#define LM_BL 27648

__global__ __launch_bounds__(256) void lin_mma(MJobs P,
        const __nv_bfloat16* __restrict__ wth, const __nv_bfloat16* __restrict__ wtl) {
    __shared__ char sm[36864];
    unsigned sb = smem_u32(sm);
    int bid = blockIdx.x;
    int sel = 0;
    #pragma unroll
    for (int i = 1; i < 5; i++)
        if (i < P.n && bid >= P.j[i].blkStart) sel = i;
    MJob J = P.j[sel];
    int rel = bid - J.blkStart;
    int rb = (rel / J.colBlks) * 64, cb = (rel % J.colBlks) * 64;

    int t = threadIdx.x, lane = t & 31, warp = t >> 5;
    int mt = warp >> 1, nh = warp & 1;
    int ltile = lane >> 3, lrow = lane & 7;
    int rowA = mt * 16 + ((ltile & 1) << 3) + lrow;
    unsigned colA = (unsigned)((ltile >> 1) * 16);
    int rowBl = ((ltile >> 1) << 3) + lrow;
    unsigned colB = (unsigned)((ltile & 1) * 16);
    int crow = lane >> 2, ccol = (lane & 3) * 2;

    float accf[4][4];
    #pragma unroll
    for (int nt = 0; nt < 4; nt++)
        #pragma unroll
        for (int p = 0; p < 4; p++) accf[nt][p] = 0.f;

    #pragma unroll 1
    for (int ph = 0; ph < 2; ph++) {
        const float* A = ph ? J.A2 : J.A;
        if (!A) break;
        int K  = ph ? J.K2 : J.K;
        int KP = ph ? J.KP2 : J.KP;
        int woff = ph ? J.woff2 : J.woff;
        const float* dscaleA = ph ? 0 : J.degpA;
        for (int k0 = 0; k0 < KP; k0 += 64) {
            __syncthreads();
            #pragma unroll 1
            for (int it = 0; it < 8; it++) {
                int f2 = t + it * 256;
                int r = f2 >> 5, q = f2 & 31;
                int kg = k0 + q * 2;
                float2 v = (kg < K) ? *(const float2*)&A[(size_t)(rb + r) * K + kg]
                                    : make_float2(0.f, 0.f);
                if (dscaleA) {
                    float sc = 1.f / fmaxf(dscaleA[rb + r], 1.f);
                    v.x *= sc; v.y *= sc;
                }
                __nv_bfloat16 h0 = __float2bfloat16(v.x), h1 = __float2bfloat16(v.y);
                float l0 = v.x - __bfloat162float(h0), l1 = v.y - __bfloat162float(h1);
                *(unsigned*)(sm + LM_AH + r * 144 + q * 4) =
                    ((unsigned)__bfloat16_as_ushort(h1) << 16) | __bfloat16_as_ushort(h0);
                *(unsigned*)(sm + LM_AL + r * 144 + q * 4) = pack_bf2(l0, l1);
            }
            #pragma unroll 1
            for (int it = 0; it < 2; it++) {
                int u4 = t + it * 256;
                int n = u4 >> 3, q = u4 & 7;
                size_t src = (size_t)woff + (size_t)(cb + n) * KP + k0 + q * 8;
                *(uint4*)(sm + LM_BH + n * 144 + q * 16) = *(const uint4*)(wth + src);
                *(uint4*)(sm + LM_BL + n * 144 + q * 16) = *(const uint4*)(wtl + src);
            }
            __syncthreads();
            #pragma unroll 1
            for (int pass = 0; pass < 3; pass++) {
                unsigned abase = sb + (pass < 2 ? LM_AH : LM_AL);
                unsigned bbase = sb + ((pass == 1) ? LM_BL : LM_BH);
                #pragma unroll
                for (int k = 0; k < 4; k++) {
                    unsigned a0, a1, a2, a3;
                    ldsm4(abase + (unsigned)rowA * 144 + colA + k * 32, a0, a1, a2, a3);
                    #pragma unroll
                    for (int ntp = 0; ntp < 2; ntp++) {
                        unsigned b0, b1, b2, b3;
                        ldsm4(bbase + (unsigned)(nh * 32 + ntp * 16 + rowBl) * 144 + colB + k * 32,
                              b0, b1, b2, b3);
                        mma_bf16(accf[ntp * 2],     a0, a1, a2, a3, b0, b1);
                        mma_bf16(accf[ntp * 2 + 1], a0, a1, a2, a3, b2, b3);
                    }
                }
            }
        }
    }

    int row0 = rb + mt * 16 + crow;
    float ds0 = J.degp ? 1.f / fmaxf(J.degp[row0], 1.f) : 1.f;
    float ds1 = J.degp ? 1.f / fmaxf(J.degp[row0 + 8], 1.f) : 1.f;
    #pragma unroll
    for (int nt = 0; nt < 4; nt++) {
        int col = cb + nh * 32 + nt * 8 + ccol;
        float bv0 = J.bias ? J.bias[col] : 0.f;
        float bv1 = J.bias ? J.bias[col + 1] : 0.f;
        float v00 = accf[nt][0] + bv0, v01 = accf[nt][1] + bv1;
        float v10 = accf[nt][2] + bv0, v11 = accf[nt][3] + bv1;
        if (J.addD) {
            v00 += J.addD[(size_t)row0 * J.N + col] * ds0;
            v01 += J.addD[(size_t)row0 * J.N + col + 1] * ds0;
            v10 += J.addD[(size_t)(row0 + 8) * J.N + col] * ds1;
            v11 += J.addD[(size_t)(row0 + 8) * J.N + col + 1] * ds1;
        }
        if (J.relu) {
            v00 = fmaxf(v00, 0.f); v01 = fmaxf(v01, 0.f);
            v10 = fmaxf(v10, 0.f); v11 = fmaxf(v11, 0.f);
        }
        J.C[(size_t)row0 * J.N + col] = v00;
        J.C[(size_t)row0 * J.N + col + 1] = v01;
        J.C[(size_t)(row0 + 8) * J.N + col] = v10;
        J.C[(size_t)(row0 + 8) * J.N + col + 1] = v11;
    }
}

// ---------------- fused prep ----------------
__global__ void prep_all(
    const float* __restrict__ ha, const float* __restrict__ hp,
    const float* __restrict__ ht, const float* __restrict__ hc,
    __nv_bfloat16* __restrict__ anh, __nv_bfloat16* __restrict__ anl,
    __nv_bfloat16* __restrict__ snh, __nv_bfloat16* __restrict__ snl,
    const float* __restrict__ gp, const float* __restrict__ gt, const float* __restrict__ gc,
    const float* __restrict__ wdv, const float* __restrict__ gas,
    float* __restrict__ ald, float* __restrict__ alsp, float* __restrict__ alst,
    float* __restrict__ alsc, unsigned* __restrict__ mxsEnc,
    __nv_bfloat16* __restrict__ hsT)
{
    int m = blockIdx.x, t = threadIdx.x;
    __shared__ float ws[4];
    __shared__ float tile[32][33];
    if (m < 18432) {
        const float* X; int r; int isAu = 0; size_t off = 0;
        if (m < 4096)       { X = ha; r = m; isAu = 1; }
        else if (m < 12288) { X = hp; r = m - 4096;  off = 0; }
        else if (m < 16384) { X = ht; r = m - 12288; off = (size_t)NP * 128; }
        else                { X = hc; r = m - 16384; off = (size_t)(NP + NT) * 128; }
        float v = X[(size_t)r * 128 + t];
        float s = v * v;
        #pragma unroll
        for (int o = 16; o; o >>= 1) s += __shfl_xor_sync(0xffffffffu, s, o);
        if ((t & 31) == 0) ws[t >> 5] = s;
        __syncthreads();
        float tot = ws[0] + ws[1] + ws[2] + ws[3];
        float y = v / fmaxf(sqrtf(tot), 1e-12f);
        __nv_bfloat16 hi = __float2bfloat16(y);
        __nv_bfloat16 lo = __float2bfloat16(y - __bfloat162float(hi));
        if (isAu) {
            anh[(size_t)r * 128 + t] = hi;
            anl[(size_t)r * 128 + t] = lo;
        } else {
            snh[off + (size_t)r * 128 + t] = hi;
            snl[off + (size_t)r * 128 + t] = lo;
        }
    } else if (m < 45056) {
        int m2 = m - 18432;
        const float* X; const float* vec; float* y; int r; int mxi = -1;
        if (m2 < 12288) {
            int tpe = m2 >> 12;
            X = ha; vec = wdv + tpe * 128; y = ald + tpe * NA; r = m2 & 4095;
        } else {
            int m3 = m2 - 12288;
            if (m3 < 8192)       { X = gp; vec = gas;       y = alsp; r = m3;         mxi = 0; }
            else if (m3 < 12288) { X = gt; vec = gas + 128; y = alst; r = m3 - 8192;  mxi = 1; }
            else                 { X = gc; vec = gas + 256; y = alsc; r = m3 - 12288; mxi = 2; }
        }
        float s = X[(size_t)r * 128 + t] * vec[t];
        #pragma unroll
        for (int o = 16; o; o >>= 1) s += __shfl_xor_sync(0xffffffffu, s, o);
        if ((t & 31) == 0) ws[t >> 5] = s;
        __syncthreads();
        if (t == 0) {
            float tot = ws[0] + ws[1] + ws[2] + ws[3];
            y[r] = tot;
            if (mxi >= 0) atomicMax(&mxsEnc[mxi], enc_f(tot));
        }
    } else {
        int ti = m - 45056;
        const float* X; __nv_bfloat16* O; int Ns2, s0, d0;
        if (ti < 1024)      { X = gp; O = hsT;                          Ns2 = NP; s0 = (ti & 255) * 32; d0 = (ti >> 8) * 32; }
        else if (ti < 1536) { int u = ti - 1024; X = gt; O = hsT + (size_t)128 * NP;        Ns2 = NT; s0 = (u & 127) * 32; d0 = (u >> 7) * 32; }
        else                { int u = ti - 1536; X = gc; O = hsT + (size_t)128 * (NP + NT); Ns2 = NC; s0 = (u & 63) * 32;  d0 = (u >> 6) * 32; }
        int tx = t & 31, ty = t >> 5;
        #pragma unroll
        for (int r = 0; r < 8; r++) {
            int rr = r * 4 + ty;
            tile[rr][tx] = X[(size_t)(s0 + rr) * 128 + d0 + tx];
        }
        __syncthreads();
        #pragma unroll
        for (int r = 0; r < 8; r++) {
            int dd = r * 4 + ty;
            O[(size_t)(d0 + dd) * Ns2 + s0 + tx] = __float2bfloat16(tile[tx][dd]);
        }
    }
}

// ---------------- HMMA hetero GAT: 512 threads (16 warps = 4 mt x 4 nq), 2 CTA/SM ----------------
#define HET_GRID 304
#define SA_ANH 0
#define SA_ANL 17408
#define SA_SNH 34816
#define SA_SNL 52224
#define SA_HST 69632
#define SA_W   88064
#define SA_ALD 97280
#define SA_ALS 97536
#define SA_TOT 97792

__global__ __launch_bounds__(512, 2) void hetero_mma(
    const __nv_bfloat16* __restrict__ anh, const __nv_bfloat16* __restrict__ anl,
    const float* __restrict__ ald3, const unsigned* __restrict__ mxsEnc,
    const __nv_bfloat16* __restrict__ snh, const __nv_bfloat16* __restrict__ snl,
    const __nv_bfloat16* __restrict__ hsT,
    const float* __restrict__ alsp, const float* __restrict__ alst,
    const float* __restrict__ alsc,
    float* __restrict__ acc, float* __restrict__ deng)
{
    extern __shared__ char sm[];
    unsigned sb = smem_u32(sm);
    float* sALD = (float*)(sm + SA_ALD);
    float* sALS = (float*)(sm + SA_ALS);

    int t = threadIdx.x, lane = t & 31, warp = t >> 5;
    int mt = warp >> 2, nq = warp & 3;
    int ltile = lane >> 3, lrow = lane & 7;
    int rowA = mt * 16 + ((ltile & 1) << 3) + lrow;
    unsigned colA = (unsigned)((ltile >> 1) * 16);
    int rowBl = ((ltile >> 1) << 3) + lrow;
    unsigned colB = (unsigned)((ltile & 1) * 16);
    int crow = lane >> 2;
    int ccol = (lane & 3) * 2;

    const int TOTC = 14336;
    int cs = (int)(((long long)blockIdx.x * TOTC) / HET_GRID);
    int ce = (int)(((long long)(blockIdx.x + 1) * TOTC) / HET_GRID);

    int curType = -1, curAb = -1, r0g = 0;
    const __nv_bfloat16 *snhT = snh, *snlT = snl, *hsTT = hsT;
    const float* alsT = alsp;
    int Ns = NP;
    float mx = 0.f, ald0 = 0.f, ald1 = 0.f, mrow0 = 0.f, mrow1 = 0.f;
    float den0 = 0.f, den1 = 0.f;
    float acc2[4][4];

    for (int c = cs; c < ce; c++) {
        int type, ab, ch;
        if (c < 8192)       { type = 0; ab = c >> 7; ch = c & 127; }
        else if (c < 12288) { int u = c - 8192;  type = 1; ab = u >> 6; ch = u & 63; }
        else                { int u = c - 12288; type = 2; ab = u >> 5; ch = u & 31; }
        int j0 = ch << 6;

        if (type != curType || ab != curAb) {
            if (curType >= 0) {
                int gr0 = r0g + mt * 16 + crow;
                #pragma unroll
                for (int nt = 0; nt < 4; nt++) {
                    int d = nq * 32 + nt * 8 + ccol;
                    float* b0 = acc + ((size_t)curType * NA + gr0) * 128 + d;
                    float* b1 = acc + ((size_t)curType * NA + gr0 + 8) * 128 + d;
                    atomicAdd(b0, acc2[nt][0]); atomicAdd(b0 + 1, acc2[nt][1]);
                    atomicAdd(b1, acc2[nt][2]); atomicAdd(b1 + 1, acc2[nt][3]);
                }
                float d0 = den0 + __shfl_xor_sync(0xffffffffu, den0, 1);
                d0 += __shfl_xor_sync(0xffffffffu, d0, 2);
                float d1 = den1 + __shfl_xor_sync(0xffffffffu, den1, 1);
                d1 += __shfl_xor_sync(0xffffffffu, d1, 2);
                if ((lane & 3) == 0) {
                    atomicAdd(deng + curType * NA + gr0, d0);
                    atomicAdd(deng + curType * NA + gr0 + 8, d1);
                }
            }
            curType = type; curAb = ab; r0g = ab << 6;
            if (type == 0)      { snhT = snh; snlT = snl; hsTT = hsT; alsT = alsp; Ns = NP; }
            else if (type == 1) { snhT = snh + (size_t)NP * 128; snlT = snl + (size_t)NP * 128;
                                  hsTT = hsT + (size_t)128 * NP; alsT = alst; Ns = NT; }
            else                { snhT = snh + (size_t)(NP + NT) * 128; snlT = snl + (size_t)(NP + NT) * 128;
                                  hsTT = hsT + (size_t)128 * (NP + NT); alsT = alsc; Ns = NC; }
            mx = dec_f(mxsEnc[type]);
            __syncthreads();
            for (int i = t; i < 1024; i += 512) {
                int r = i >> 4, q = i & 15;
                cp16(sb + SA_ANH + r * 272 + q * 16, anh + (size_t)(r0g + r) * 128 + q * 8);
                cp16(sb + SA_ANL + r * 272 + q * 16, anl + (size_t)(r0g + r) * 128 + q * 8);
            }
            if (t < 16) cp16(sb + SA_ALD + t * 16, ald3 + type * NA + r0g + t * 4);
            CP_WAIT();
            __syncthreads();
            ald0 = sALD[mt * 16 + crow];
            ald1 = sALD[mt * 16 + crow + 8];
            float tm0 = ald0 + mx; mrow0 = tm0 >= 0.f ? tm0 : 0.2f * tm0;
            float tm1 = ald1 + mx; mrow1 = tm1 >= 0.f ? tm1 : 0.2f * tm1;
            den0 = den1 = 0.f;
            #pragma unroll
            for (int nt = 0; nt < 4; nt++)
                #pragma unroll
                for (int p = 0; p < 4; p++) acc2[nt][p] = 0.f;
        }

        __syncthreads();
        for (int i = t; i < 1024; i += 512) {
            int r = i >> 4, q = i & 15;
            cp16(sb + SA_SNH + r * 272 + q * 16, snhT + (size_t)(j0 + r) * 128 + q * 8);
            cp16(sb + SA_SNL + r * 272 + q * 16, snlT + (size_t)(j0 + r) * 128 + q * 8);
            int hd = i >> 3, hq = i & 7;
            cp16(sb + SA_HST + hd * 144 + hq * 16, hsTT + (size_t)hd * Ns + j0 + hq * 8);
        }
        if (t < 16) cp16(sb + SA_ALS + t * 16, alsT + j0 + t * 4);
        CP_WAIT();
        __syncthreads();

        // phase 1: S tile rows mt*16, cols nq*16
        float acc1[2][4];
        #pragma unroll
        for (int nt = 0; nt < 2; nt++)
            #pragma unroll
            for (int p = 0; p < 4; p++) acc1[nt][p] = 0.f;
        #pragma unroll 1
        for (int pass = 0; pass < 3; pass++) {
            unsigned abase = sb + (pass < 2 ? SA_ANH : SA_ANL);
            unsigned bbase = sb + (pass == 1 ? SA_SNL : SA_SNH);
            #pragma unroll
            for (int k = 0; k < 8; k++) {
                unsigned a0, a1, a2, a3;
                ldsm4(abase + (unsigned)rowA * 272 + colA + k * 32, a0, a1, a2, a3);
                unsigned b0, b1, b2, b3;
                ldsm4(bbase + (unsigned)(nq * 16 + rowBl) * 272 + colB + k * 32,
                      b0, b1, b2, b3);
                mma_bf16(acc1[0], a0, a1, a2, a3, b0, b1);
                mma_bf16(acc1[1], a0, a1, a2, a3, b2, b3);
            }
        }

        int gr0 = r0g + mt * 16 + crow;
        #pragma unroll
        for (int nt = 0; nt < 2; nt++) {
            int jl = nq * 16 + nt * 8 + ccol;
            int jg = j0 + jl;
            float als0 = sALS[jl], als1 = sALS[jl + 1];
            float e0 = ald0 + als0; e0 = e0 >= 0.f ? e0 : 0.2f * e0;
            float e1 = ald0 + als1; e1 = e1 >= 0.f ? e1 : 0.2f * e1;
            float f0 = ald1 + als0; f0 = f0 >= 0.f ? f0 : 0.2f * f0;
            float f1 = ald1 + als1; f1 = f1 >= 0.f ? f1 : 0.2f * f1;
            float w00 = (acc1[nt][0] > 0.1f && gr0 != jg)         ? __expf(e0 - mrow0) : 0.f;
            float w01 = (acc1[nt][1] > 0.1f && gr0 != jg + 1)     ? __expf(e1 - mrow0) : 0.f;
            float w10 = (acc1[nt][2] > 0.1f && gr0 + 8 != jg)     ? __expf(f0 - mrow1) : 0.f;
            float w11 = (acc1[nt][3] > 0.1f && gr0 + 8 != jg + 1) ? __expf(f1 - mrow1) : 0.f;
            __nv_bfloat16 b00 = __float2bfloat16(w00), b01 = __float2bfloat16(w01);
            __nv_bfloat16 b10 = __float2bfloat16(w10), b11 = __float2bfloat16(w11);
            den0 += __bfloat162float(b00) + __bfloat162float(b01);
            den1 += __bfloat162float(b10) + __bfloat162float(b11);
            unsigned p0 = ((unsigned)__bfloat16_as_ushort(b01) << 16) | __bfloat16_as_ushort(b00);
            unsigned p1 = ((unsigned)__bfloat16_as_ushort(b11) << 16) | __bfloat16_as_ushort(b10);
            int r0l = mt * 16 + crow;
            *(unsigned*)(sm + SA_W + r0l * 144 + jl * 2) = p0;
            *(unsigned*)(sm + SA_W + (r0l + 8) * 144 + jl * 2) = p1;
        }
        __syncthreads();

        // phase 2: NUM rows mt*16, dims nq*32
        #pragma unroll
        for (int k = 0; k < 4; k++) {
            unsigned a0, a1, a2, a3;
            ldsm4(sb + SA_W + (unsigned)rowA * 144 + colA + k * 32, a0, a1, a2, a3);
            #pragma unroll
            for (int ntp = 0; ntp < 2; ntp++) {
                unsigned b0, b1, b2, b3;
                ldsm4(sb + SA_HST + (unsigned)(nq * 32 + ntp * 16 + rowBl) * 144 + colB + k * 32,
                      b0, b1, b2, b3);
                mma_bf16(acc2[ntp * 2],     a0, a1, a2, a3, b0, b1);
                mma_bf16(acc2[ntp * 2 + 1], a0, a1, a2, a3, b2, b3);
            }
        }
    }

    if (curType >= 0) {
        int gr0 = r0g + mt * 16 + crow;
        #pragma unroll
        for (int nt = 0; nt < 4; nt++) {
            int d = nq * 32 + nt * 8 + ccol;
            float* b0 = acc + ((size_t)curType * NA + gr0) * 128 + d;
            float* b1 = acc + ((size_t)curType * NA + gr0 + 8) * 128 + d;
            atomicAdd(b0, acc2[nt][0]); atomicAdd(b0 + 1, acc2[nt][1]);
            atomicAdd(b1, acc2[nt][2]); atomicAdd(b1 + 1, acc2[nt][3]);
        }
        float d0 = den0 + __shfl_xor_sync(0xffffffffu, den0, 1);
        d0 += __shfl_xor_sync(0xffffffffu, d0, 2);
        float d1 = den1 + __shfl_xor_sync(0xffffffffu, den1, 1);
        d1 += __shfl_xor_sync(0xffffffffu, d1, 2);
        if ((lane & 3) == 0) {
            atomicAdd(deng + curType * NA + gr0, d0);
            atomicAdd(deng + curType * NA + gr0 + 8, d1);
        }
    }
}

// attscore with fused finalize
__global__ void attscore_kernel(float* __restrict__ acc, const float* __restrict__ den,
                                const float* __restrict__ gb,
                                const float* __restrict__ xt,
                                const float* __restrict__ Watt, const float* __restrict__ atts,
                                float* __restrict__ ssum) {
    int set = blockIdx.y;
    int rb = blockIdx.x * 4, t = threadIdx.x, c = t & 63;
    __shared__ float xs[4][128];
    if (set < 3) {
        for (int i = t; i < 512; i += 256) {
            int rr = i >> 7, cc = i & 127;
            size_t idx = ((size_t)set * NA + rb + rr) * 128 + cc;
            float d = den[set * NA + rb + rr];
            float b = gb[set * 128 + cc];
            float v = (d > 0.f) ? acc[idx] / d + b : b;
            acc[idx] = v;
            xs[rr][cc] = v;
        }
    } else {
        for (int i = t; i < 512; i += 256)
            xs[i >> 7][i & 127] = xt[(size_t)(rb + (i >> 7)) * 128 + (i & 127)];
    }
    __syncthreads();
    const float* xr = xs[t >> 6];
    float dot = 0.f;
    #pragma unroll 8
    for (int k = 0; k < 128; k++) dot += xr[k] * Watt[k * 64 + c];
    float val = (1.f / (1.f + __expf(-dot))) * atts[set * 64 + c];
    #pragma unroll
    for (int o = 16; o; o >>= 1) val += __shfl_xor_sync(0xffffffffu, val, o);
    __shared__ float ps[8];
    if ((t & 31) == 0) ps[t >> 5] = val;
    __syncthreads();
    if (t == 0) {
        float s = 0.f;
        #pragma unroll
        for (int i = 0; i < 8; i++) s += ps[i];
        atomicAdd(&ssum[set], s);
    }
}

__global__ void alpha_kernel(const float* __restrict__ ssum, float* __restrict__ alpha) {
    if (threadIdx.x == 0) {
        float s[4], m = -3e38f;
        for (int i = 0; i < 4; i++) { s[i] = ssum[i] / (float)NA; m = fmaxf(m, s[i]); }
        float e[4], tot = 0.f;
        for (int i = 0; i < 4; i++) { e[i] = expf(s[i] - m); tot += e[i]; }
        for (int i = 0; i < 4; i++) alpha[i] = e[i] / tot;
    }
}

__global__ void xatt_kernel(const float* __restrict__ heter, const float* __restrict__ xt,
                            const float* __restrict__ alpha, float* __restrict__ out) {
    int idx = blockIdx.x * blockDim.x + threadIdx.x;
    if (idx >= NA * 128) return;
    out[idx] = alpha[0] * heter[idx] + alpha[1] * heter[NA * 128 + idx] +
               alpha[2] * heter[2 * NA * 128 + idx] + alpha[3] * xt[idx];
}

__global__ void degscatter_kernel(const float* __restrict__ X, const int* __restrict__ edge,
                                  float* __restrict__ deg, float* __restrict__ AGG, int E) {
    int idx = blockIdx.x * blockDim.x + threadIdx.x;
    if (idx < E) atomicAdd(&deg[edge[E + idx]], 1.0f);
    int sidx = idx - ((E + 255) & ~255);
    if (sidx < 0 || sidx >= E * 32) return;
    int e = sidx >> 5, q = sidx & 31;
    int s = edge[e], d = edge[E + e];
    float4 v = *(const float4*)&X[(size_t)s * 128 + q * 4];
    float* o = &AGG[(size_t)d * 128 + q * 4];
    atomicAdd(o + 0, v.x); atomicAdd(o + 1, v.y);
    atomicAdd(o + 2, v.z); atomicAdd(o + 3, v.w);
}

__global__ void scatter_kernel(const float* __restrict__ X, const int* __restrict__ src,
                               const int* __restrict__ dst, float* __restrict__ AGG,
                               int E, int C) {
    int idx = blockIdx.x * blockDim.x + threadIdx.x;
    int per = C >> 2;
    if (idx >= E * per) return;
    int e = idx / per, q = idx - e * per;
    int s = src[e], d = dst[e];
    float4 v = *(const float4*)&X[(size_t)s * C + q * 4];
    float* o = &AGG[(size_t)d * C + q * 4];
    atomicAdd(o + 0, v.x); atomicAdd(o + 1, v.y);
    atomicAdd(o + 2, v.z); atomicAdd(o + 3, v.w);
}

extern "C" void kernel_launch(void* const* d_in, const int* in_sizes, int n_in,
                              void* d_out, int out_size) {
    const float* x_ma = (const float*)d_in[0];
    const float* x_mp = (const float*)d_in[1];
    const float* x_mt = (const float*)d_in[2];
    const float* x_mc = (const float*)d_in[3];
    const float* x_ia = (const float*)d_in[4];
    const int*   edge = (const int*)d_in[5];
    const float* Wla  = (const float*)d_in[6];  const float* bla  = (const float*)d_in[7];
    const float* Wlp  = (const float*)d_in[8];  const float* blp  = (const float*)d_in[9];
    const float* Wlt  = (const float*)d_in[10]; const float* blt  = (const float*)d_in[11];
    const float* Wlc  = (const float*)d_in[12]; const float* blc  = (const float*)d_in[13];
    const float* Wltg = (const float*)d_in[14]; const float* bltg = (const float*)d_in[15];
    const float* gWs  = (const float*)d_in[16];
    const float* gWd  = (const float*)d_in[17];
    const float* gas  = (const float*)d_in[18];
    const float* gad  = (const float*)d_in[19];
    const float* gb   = (const float*)d_in[20];
    const float* Watt = (const float*)d_in[21];
    const float* atts = (const float*)d_in[22];
    const float* W1l  = (const float*)d_in[23]; const float* b1 = (const float*)d_in[24];
    const float* W1r  = (const float*)d_in[25];
    const float* W2l  = (const float*)d_in[26]; const float* b2 = (const float*)d_in[27];
    const float* W2r  = (const float*)d_in[28];

    int E = in_sizes[5] / 2;
    int Ka = in_sizes[0] / NA, Kp = in_sizes[1] / NP, Kt = in_sizes[2] / NT;
    int Kc = in_sizes[3] / NC, Kg = in_sizes[4] / NA;

    float* out_x   = (float*)d_out;
    float* out_att = (float*)d_out + (size_t)NA * 64;

    float *ha,*hp,*ht,*hc,*xt,*gp,*gt,*gc;
    float *alsp,*alst,*alsc,*ald,*wdv,*acc,*den,*ssum,*alpha,*agg1,*deg,*h1,*q,*aggq;
    unsigned* mxsEnc;
    __nv_bfloat16 *anh,*anl,*snh,*snl,*hsT,*wth,*wtl;
    cudaGetSymbolAddress((void**)&ha,g_ha);   cudaGetSymbolAddress((void**)&hp,g_hp);
    cudaGetSymbolAddress((void**)&ht,g_ht);   cudaGetSymbolAddress((void**)&hc,g_hc);
    cudaGetSymbolAddress((void**)&xt,g_xt);
    cudaGetSymbolAddress((void**)&anh,g_anh); cudaGetSymbolAddress((void**)&anl,g_anl);
    cudaGetSymbolAddress((void**)&snh,g_snh); cudaGetSymbolAddress((void**)&snl,g_snl);
    cudaGetSymbolAddress((void**)&hsT,g_hsT); cudaGetSymbolAddress((void**)&gp,g_gp);
    cudaGetSymbolAddress((void**)&gt,g_gt);   cudaGetSymbolAddress((void**)&gc,g_gc);
    cudaGetSymbolAddress((void**)&alsp,g_alsp); cudaGetSymbolAddress((void**)&alst,g_alst);
    cudaGetSymbolAddress((void**)&alsc,g_alsc); cudaGetSymbolAddress((void**)&ald,g_ald);
    cudaGetSymbolAddress((void**)&wdv,g_wdv);   cudaGetSymbolAddress((void**)&mxsEnc,g_mxsEnc);
    cudaGetSymbolAddress((void**)&acc,g_acc);   cudaGetSymbolAddress((void**)&den,g_den);
    cudaGetSymbolAddress((void**)&ssum,g_ssum); cudaGetSymbolAddress((void**)&alpha,g_alpha);
    cudaGetSymbolAddress((void**)&agg1,g_agg1); cudaGetSymbolAddress((void**)&deg,g_deg);
    cudaGetSymbolAddress((void**)&h1,g_h1);     cudaGetSymbolAddress((void**)&q,g_q);
    cudaGetSymbolAddress((void**)&aggq,g_aggq);
    cudaGetSymbolAddress((void**)&wth,g_wth);   cudaGetSymbolAddress((void**)&wtl,g_wtl);

    WJobs WP; int off = 0;
    auto wj = [&](const float* W, int K, int KP, int N, int slot) {
        WP.j[slot] = {W, K, KP, N, off}; off += KP * N;
    };
    wj(gWs + 0*16384, 128, 128, 128, 0);
    wj(gWs + 1*16384, 128, 128, 128, 1);
    wj(gWs + 2*16384, 128, 128, 128, 2);
    wj(W1l, 128, 128, 256, 3);  wj(W1r, 128, 128, 256, 4);
    wj(W2l, 256, 256, 64, 5);   wj(W2r, 256, 256, 64, 6);
    WP.total = off;
    WP.j[7] = {nullptr, 0, 1, 1, off};

    auto mj = [](const float*A, int woff, int K, int KP,
                 const float*A2, int woff2, int K2, int KP2,
                 const float*bias, const float*addD, const float*degp,
                 const float*degpA, float*C,
                 int M, int N, int relu, int colBlks, int blkStart) {
        MJob J; J.A=A; J.woff=woff; J.K=K; J.KP=KP;
        J.A2=A2; J.woff2=woff2; J.K2=K2; J.KP2=KP2;
        J.bias=bias; J.addD=addD; J.degp=degp; J.degpA=degpA; J.C=C;
        J.M=M; J.N=N; J.relu=relu; J.colBlks=colBlks; J.blkStart=blkStart;
        return J;
    };

    zero_wvec<<<9284,256>>>(acc, agg1, aggq, den, deg, ssum, mxsEnc, gWd, gad, wdv);
    wprep<<<(WP.total + 255) / 256, 256>>>(WP, wth, wtl);
    {
        LJobs B; B.n = 5;
        B.j[0] = {x_ma, Wla,  bla,  ha, Ka, 0};
        B.j[1] = {x_mp, Wlp,  blp,  hp, Kp, 64};
        B.j[2] = {x_mt, Wlt,  blt,  ht, Kt, 192};
        B.j[3] = {x_mc, Wlc,  blc,  hc, Kc, 256};
        B.j[4] = {x_ia, Wltg, bltg, xt, Kg, 288};
        lin_f32<<<352,256>>>(B);
    }
    {
        MJobs B; B.n = 3;
        B.j[0] = mj(hp, WP.j[0].off, 128, 128, 0,0,0,0, 0,0,0,0, gp, NP, 128, 0, 2, 0);
        B.j[1] = mj(ht, WP.j[1].off, 128, 128, 0,0,0,0, 0,0,0,0, gt, NT, 128, 0, 2, 256);
        B.j[2] = mj(hc, WP.j[2].off, 128, 128, 0,0,0,0, 0,0,0,0, gc, NC, 128, 0, 2, 384);
        lin_mma<<<448,256>>>(B, wth, wtl);
    }
    prep_all<<<46848,128>>>(ha, hp, ht, hc, anh, anl, snh, snl,
                            gp, gt, gc, wdv, gas, ald, alsp, alst, alsc, mxsEnc, hsT);
    cudaFuncSetAttribute(hetero_mma, cudaFuncAttributeMaxDynamicSharedMemorySize, SA_TOT);
    hetero_mma<<<HET_GRID,512,SA_TOT>>>(anh, anl, ald, mxsEnc, snh, snl, hsT,
                                        alsp, alst, alsc, acc, den);
    attscore_kernel<<<dim3(NA/4,4),256>>>(acc, den, gb, xt, Watt, atts, ssum);
    alpha_kernel<<<1,32>>>(ssum, alpha);
    xatt_kernel<<<(NA*128)/256,256>>>(acc, xt, alpha, out_att);
    {
        int degBlocks = (E + 255) / 256;
        int scatBlocks = (E * 32) / 256;
        degscatter_kernel<<<degBlocks + scatBlocks, 256>>>(ha, edge, deg, agg1, E);
    }
    {
        MJobs B; B.n = 1;
        B.j[0] = mj(agg1, WP.j[3].off, 128, 128, ha, WP.j[4].off, 128, 128,
                    b1, 0, 0, deg, h1, NA, 256, 1, 4, 0);
        lin_mma<<<256,256>>>(B, wth, wtl);
    }
    {
        MJobs B; B.n = 1;
        B.j[0] = mj(h1, WP.j[5].off, 256, 256, 0,0,0,0, 0,0,0,0, q, NA, 64, 0, 1, 0);
        lin_mma<<<64,256>>>(B, wth, wtl);
    }
    scatter_kernel<<<(E*16)/256,256>>>(q, edge, edge + E, aggq, E, 64);
    {
        MJobs B; B.n = 1;
        B.j[0] = mj(h1, WP.j[6].off, 256, 256, 0,0,0,0, b2, aggq, deg, 0, out_x, NA, 64, 0, 1, 0);
        lin_mma<<<64,256>>>(B, wth, wtl);
    }
}

// round 17
// speedup vs baseline: 1.0409x; 1.0409x over previous
#include <cuda_runtime.h>
#include <cuda_bf16.h>
#include <math.h>

#define NA 4096
#define NP 8192
#define NT 4096
#define NC 2048
typedef unsigned long long ull;

// ---------------- device scratch ----------------
__device__ float g_ha[NA*128];
__device__ float g_hp[NP*128];
__device__ float g_ht[NT*128];
__device__ float g_hc[NC*128];
__device__ float g_xt[NA*128];
__device__ __nv_bfloat16 g_anh[NA*128];
__device__ __nv_bfloat16 g_anl[NA*128];
__device__ __nv_bfloat16 g_snh[(NP+NT+NC)*128];
__device__ __nv_bfloat16 g_snl[(NP+NT+NC)*128];
__device__ __nv_bfloat16 g_hsT[(NP+NT+NC)*128];
__device__ float g_gp[NP*128];
__device__ float g_gt[NT*128];
__device__ float g_gc[NC*128];
__device__ float g_alsp[NP];
__device__ float g_alst[NT];
__device__ float g_alsc[NC];
__device__ float g_ald[3*NA];
__device__ float g_wdv[3*128];
__device__ unsigned g_mxsEnc[3];
__device__ float g_acc[3*NA*128];
__device__ float g_den[3*NA];
__device__ float g_ssum[4];
__device__ float g_alpha[4];
__device__ float g_agg1[NA*128];
__device__ float g_deg[NA];
__device__ float g_h1[NA*256];
__device__ float g_q[NA*64];
__device__ float g_aggq[NA*64];
__device__ __nv_bfloat16 g_wth[147456];
__device__ __nv_bfloat16 g_wtl[147456];

__device__ __forceinline__ unsigned enc_f(float f) {
    unsigned b = __float_as_uint(f);
    return (b & 0x80000000u) ? ~b : (b | 0x80000000u);
}
__device__ __forceinline__ float dec_f(unsigned u) {
    unsigned b = (u & 0x80000000u) ? (u ^ 0x80000000u) : ~u;
    return __uint_as_float(b);
}
__device__ __forceinline__ unsigned smem_u32(const void* p) {
    unsigned a;
    asm("{ .reg .u64 t; cvta.to.shared.u64 t, %1; cvt.u32.u64 %0, t; }" : "=r"(a) : "l"(p));
    return a;
}
__device__ __forceinline__ void fma2(ull& d, ull a, ull b) {
    asm("fma.rn.f32x2 %0, %1, %2, %0;" : "+l"(d) : "l"(a), "l"(b));
}
__device__ __forceinline__ ull packf2(float x, float y) {
    ull r; asm("mov.b64 %0, {%1, %2};" : "=l"(r) : "f"(x), "f"(y)); return r;
}
__device__ __forceinline__ float2 unpackf2(ull v) {
    float2 r; asm("mov.b64 {%0, %1}, %2;" : "=f"(r.x), "=f"(r.y) : "l"(v)); return r;
}
__device__ __forceinline__ void ldsm4(unsigned addr, unsigned& r0, unsigned& r1,
                                      unsigned& r2, unsigned& r3) {
    asm volatile("ldmatrix.sync.aligned.m8n8.x4.shared.b16 {%0,%1,%2,%3},[%4];"
                 : "=r"(r0), "=r"(r1), "=r"(r2), "=r"(r3) : "r"(addr));
}
__device__ __forceinline__ void mma_bf16(float* d, unsigned a0, unsigned a1,
                                         unsigned a2, unsigned a3,
                                         unsigned b0, unsigned b1) {
    asm volatile(
        "mma.sync.aligned.m16n8k16.row.col.f32.bf16.bf16.f32 "
        "{%0,%1,%2,%3},{%4,%5,%6,%7},{%8,%9},{%0,%1,%2,%3};"
        : "+f"(d[0]), "+f"(d[1]), "+f"(d[2]), "+f"(d[3])
        : "r"(a0), "r"(a1), "r"(a2), "r"(a3), "r"(b0), "r"(b1));
}
__device__ __forceinline__ unsigned pack_bf2(float a, float b) {
    __nv_bfloat16 x = __float2bfloat16(a), y = __float2bfloat16(b);
    return ((unsigned)__bfloat16_as_ushort(y) << 16) | __bfloat16_as_ushort(x);
}
__device__ __forceinline__ void cp16(unsigned dst, const void* src) {
    asm volatile("cp.async.cg.shared.global [%0], [%1], 16;" :: "r"(dst), "l"(src));
}
#define CP_WAIT() asm volatile("cp.async.commit_group;\ncp.async.wait_group 0;" ::: "memory")

// ---------------- fused zero init (float4) + wvec ----------------
__global__ void zero_wvec(float* __restrict__ acc, float* __restrict__ agg1,
                          float* __restrict__ aggq, float* __restrict__ den,
                          float* __restrict__ deg, float* __restrict__ ssum,
                          unsigned* __restrict__ mxsEnc,
                          const float* __restrict__ W3, const float* __restrict__ a3,
                          float* __restrict__ wdv) {
    if (blockIdx.x >= 2321) {
        int i = blockIdx.x - 2321, k = threadIdx.x;
        __shared__ float sa[128];
        if (k < 128) sa[k] = a3[i * 128 + k];
        __syncthreads();
        if (k < 128) {
            const float* W = W3 + (size_t)i * 16384 + (size_t)k * 128;
            float s = 0.f;
            #pragma unroll 8
            for (int c = 0; c < 128; c++) s += W[c] * sa[c];
            wdv[i * 128 + k] = s;
        }
        return;
    }
    int i = blockIdx.x * 256 + threadIdx.x;
    float4 z = make_float4(0.f, 0.f, 0.f, 0.f);
    if (i < 393216) { ((float4*)acc)[i] = z; return; }
    i -= 393216; if (i < 131072) { ((float4*)agg1)[i] = z; return; }
    i -= 131072; if (i < 65536)  { ((float4*)aggq)[i] = z; return; }
    i -= 65536;  if (i < 3072)   { ((float4*)den)[i] = z; return; }
    i -= 3072;   if (i < 1024)   { ((float4*)deg)[i] = z; return; }
    i -= 1024;   if (i < 4)      { ssum[i] = 0.f; return; }
    i -= 4;      if (i < 3)      mxsEnc[i] = enc_f(-3.0e38f);
}

// ---------------- wprep ----------------
struct WJob { const float* W; int K, KP, N, off; };
struct WJobs { WJob j[8]; int total; };

__global__ void wprep(WJobs P, __nv_bfloat16* __restrict__ wth,
                      __nv_bfloat16* __restrict__ wtl) {
    int idx = blockIdx.x * 256 + threadIdx.x;
    if (idx >= P.total) return;
    int sel = 0;
    #pragma unroll
    for (int i = 1; i < 8; i++)
        if (idx >= P.j[i].off) sel = i;
    WJob J = P.j[sel];
    int local = idx - J.off;
    int n = local / J.KP, k = local - n * J.KP;
    float v = (k < J.K) ? J.W[(size_t)k * J.N + n] : 0.f;
    __nv_bfloat16 hi = __float2bfloat16(v);
    __nv_bfloat16 lo = __float2bfloat16(v - __bfloat162float(hi));
    wth[idx] = hi;
    wtl[idx] = lo;
}

// ---------------- fp32 SIMT linear, f32x2 inner ----------------
struct LJob { const float *A, *W, *bias; float* C; int K, blkStart; };
struct LJobs { LJob j[5]; int n; };

__global__ __launch_bounds__(256) void lin_f32(LJobs P) {
    __shared__ __align__(16) float As[16][64];
    __shared__ __align__(16) float Ws[16][128];
    int bid = blockIdx.x;
    int sel = 0;
    #pragma unroll
    for (int i = 1; i < 5; i++)
        if (i < P.n && bid >= P.j[i].blkStart) sel = i;
    LJob J = P.j[sel];
    int rb = (bid - J.blkStart) * 64;
    int K = J.K;
    int t = threadIdx.x, cg = t & 31, rg = t >> 5;
    ull acc2[8][2];
    #pragma unroll
    for (int i = 0; i < 8; i++) { acc2[i][0] = 0ull; acc2[i][1] = 0ull; }

    for (int k0 = 0; k0 < K; k0 += 16) {
        for (int i = t; i < 1024; i += 256) {
            int r = i >> 4, kk = i & 15, kg = k0 + kk;
            As[kk][r] = (kg < K) ? J.A[(size_t)(rb + r) * K + kg] : 0.f;
        }
        for (int i = t; i < 512; i += 256) {
            int kk = i >> 5, cq = i & 31, kg = k0 + kk;
            float4 w = (kg < K) ? *(const float4*)&J.W[(size_t)kg * 128 + cq * 4]
                                : make_float4(0.f, 0.f, 0.f, 0.f);
            *(float4*)&Ws[kk][cq * 4] = w;
        }
        __syncthreads();
        #pragma unroll
        for (int kk = 0; kk < 16; kk++) {
            ulonglong2 w2 = *(ulonglong2*)&Ws[kk][cg * 4];
            #pragma unroll
            for (int i = 0; i < 8; i++) {
                float a = As[kk][rg * 8 + i];
                ull ap = packf2(a, a);
                fma2(acc2[i][0], ap, w2.x);
                fma2(acc2[i][1], ap, w2.y);
            }
        }
        __syncthreads();
    }
    #pragma unroll
    for (int i = 0; i < 8; i++) {
        int row = rb + rg * 8 + i;
        float2 v01 = unpackf2(acc2[i][0]);
        float2 v23 = unpackf2(acc2[i][1]);
        int col = cg * 4;
        J.C[(size_t)row * 128 + col]     = v01.x + J.bias[col];
        J.C[(size_t)row * 128 + col + 1] = v01.y + J.bias[col + 1];
        J.C[(size_t)row * 128 + col + 2] = v23.x + J.bias[col + 2];
        J.C[(size_t)row * 128 + col + 3] = v23.y + J.bias[col + 3];
    }
}

// ---------------- batched HMMA linear (3-pass bf16 split) ----------------
struct MJob {
    const float *A, *A2, *bias, *addD, *degp, *degpA;
    float* C;
    int woff, woff2, M, K, K2, KP, KP2, N, relu, colBlks, blkStart;
};
struct MJobs { MJob j[5]; int n; };

#define LM_AH 0
#define LM_AL 9216
#define LM_BH 18432
#define LM_BL 27648

__global__ __launch_bounds__(256) void lin_mma(MJobs P,
        const __nv_bfloat16* __restrict__ wth, const __nv_bfloat16* __restrict__ wtl) {
    __shared__ char sm[36864];
    unsigned sb = smem_u32(sm);
    int bid = blockIdx.x;
    int sel = 0;
    #pragma unroll
    for (int i = 1; i < 5; i++)
        if (i < P.n && bid >= P.j[i].blkStart) sel = i;
    MJob J = P.j[sel];
    int rel = bid - J.blkStart;
    int rb = (rel / J.colBlks) * 64, cb = (rel % J.colBlks) * 64;

    int t = threadIdx.x, lane = t & 31, warp = t >> 5;
    int mt = warp >> 1, nh = warp & 1;
    int ltile = lane >> 3, lrow = lane & 7;
    int rowA = mt * 16 + ((ltile & 1) << 3) + lrow;
    unsigned colA = (unsigned)((ltile >> 1) * 16);
    int rowBl = ((ltile >> 1) << 3) + lrow;
    unsigned colB = (unsigned)((ltile & 1) * 16);
    int crow = lane >> 2, ccol = (lane & 3) * 2;

    float accf[4][4];
    #pragma unroll
    for (int nt = 0; nt < 4; nt++)
        #pragma unroll
        for (int p = 0; p < 4; p++) accf[nt][p] = 0.f;

    #pragma unroll 1
    for (int ph = 0; ph < 2; ph++) {
        const float* A = ph ? J.A2 : J.A;
        if (!A) break;
        int K  = ph ? J.K2 : J.K;
        int KP = ph ? J.KP2 : J.KP;
        int woff = ph ? J.woff2 : J.woff;
        const float* dscaleA = ph ? 0 : J.degpA;
        for (int k0 = 0; k0 < KP; k0 += 64) {
            __syncthreads();
            #pragma unroll 1
            for (int it = 0; it < 8; it++) {
                int f2 = t + it * 256;
                int r = f2 >> 5, q = f2 & 31;
                int kg = k0 + q * 2;
                float2 v = (kg < K) ? *(const float2*)&A[(size_t)(rb + r) * K + kg]
                                    : make_float2(0.f, 0.f);
                if (dscaleA) {
                    float sc = 1.f / fmaxf(dscaleA[rb + r], 1.f);
                    v.x *= sc; v.y *= sc;
                }
                __nv_bfloat16 h0 = __float2bfloat16(v.x), h1 = __float2bfloat16(v.y);
                float l0 = v.x - __bfloat162float(h0), l1 = v.y - __bfloat162float(h1);
                *(unsigned*)(sm + LM_AH + r * 144 + q * 4) =
                    ((unsigned)__bfloat16_as_ushort(h1) << 16) | __bfloat16_as_ushort(h0);
                *(unsigned*)(sm + LM_AL + r * 144 + q * 4) = pack_bf2(l0, l1);
            }
            #pragma unroll 1
            for (int it = 0; it < 2; it++) {
                int u4 = t + it * 256;
                int n = u4 >> 3, q = u4 & 7;
                size_t src = (size_t)woff + (size_t)(cb + n) * KP + k0 + q * 8;
                *(uint4*)(sm + LM_BH + n * 144 + q * 16) = *(const uint4*)(wth + src);
                *(uint4*)(sm + LM_BL + n * 144 + q * 16) = *(const uint4*)(wtl + src);
            }
            __syncthreads();
            #pragma unroll 1
            for (int pass = 0; pass < 3; pass++) {
                unsigned abase = sb + (pass < 2 ? LM_AH : LM_AL);
                unsigned bbase = sb + ((pass == 1) ? LM_BL : LM_BH);
                #pragma unroll
                for (int k = 0; k < 4; k++) {
                    unsigned a0, a1, a2, a3;
                    ldsm4(abase + (unsigned)rowA * 144 + colA + k * 32, a0, a1, a2, a3);
                    #pragma unroll
                    for (int ntp = 0; ntp < 2; ntp++) {
                        unsigned b0, b1, b2, b3;
                        ldsm4(bbase + (unsigned)(nh * 32 + ntp * 16 + rowBl) * 144 + colB + k * 32,
                              b0, b1, b2, b3);
                        mma_bf16(accf[ntp * 2],     a0, a1, a2, a3, b0, b1);
                        mma_bf16(accf[ntp * 2 + 1], a0, a1, a2, a3, b2, b3);
                    }
                }
            }
        }
    }

    int row0 = rb + mt * 16 + crow;
    float ds0 = J.degp ? 1.f / fmaxf(J.degp[row0], 1.f) : 1.f;
    float ds1 = J.degp ? 1.f / fmaxf(J.degp[row0 + 8], 1.f) : 1.f;
    #pragma unroll
    for (int nt = 0; nt < 4; nt++) {
        int col = cb + nh * 32 + nt * 8 + ccol;
        float bv0 = J.bias ? J.bias[col] : 0.f;
        float bv1 = J.bias ? J.bias[col + 1] : 0.f;
        float v00 = accf[nt][0] + bv0, v01 = accf[nt][1] + bv1;
        float v10 = accf[nt][2] + bv0, v11 = accf[nt][3] + bv1;
        if (J.addD) {
            v00 += J.addD[(size_t)row0 * J.N + col] * ds0;
            v01 += J.addD[(size_t)row0 * J.N + col + 1] * ds0;
            v10 += J.addD[(size_t)(row0 + 8) * J.N + col] * ds1;
            v11 += J.addD[(size_t)(row0 + 8) * J.N + col + 1] * ds1;
        }
        if (J.relu) {
            v00 = fmaxf(v00, 0.f); v01 = fmaxf(v01, 0.f);
            v10 = fmaxf(v10, 0.f); v11 = fmaxf(v11, 0.f);
        }
        J.C[(size_t)row0 * J.N + col] = v00;
        J.C[(size_t)row0 * J.N + col + 1] = v01;
        J.C[(size_t)(row0 + 8) * J.N + col] = v10;
        J.C[(size_t)(row0 + 8) * J.N + col + 1] = v11;
    }
}

// ---------------- fused prep ----------------
__global__ void prep_all(
    const float* __restrict__ ha, const float* __restrict__ hp,
    const float* __restrict__ ht, const float* __restrict__ hc,
    __nv_bfloat16* __restrict__ anh, __nv_bfloat16* __restrict__ anl,
    __nv_bfloat16* __restrict__ snh, __nv_bfloat16* __restrict__ snl,
    const float* __restrict__ gp, const float* __restrict__ gt, const float* __restrict__ gc,
    const float* __restrict__ wdv, const float* __restrict__ gas,
    float* __restrict__ ald, float* __restrict__ alsp, float* __restrict__ alst,
    float* __restrict__ alsc, unsigned* __restrict__ mxsEnc,
    __nv_bfloat16* __restrict__ hsT)
{
    int m = blockIdx.x, t = threadIdx.x;
    __shared__ float ws[4];
    __shared__ float tile[32][33];
    if (m < 18432) {
        const float* X; int r; int isAu = 0; size_t off = 0;
        if (m < 4096)       { X = ha; r = m; isAu = 1; }
        else if (m < 12288) { X = hp; r = m - 4096;  off = 0; }
        else if (m < 16384) { X = ht; r = m - 12288; off = (size_t)NP * 128; }
        else                { X = hc; r = m - 16384; off = (size_t)(NP + NT) * 128; }
        float v = X[(size_t)r * 128 + t];
        float s = v * v;
        #pragma unroll
        for (int o = 16; o; o >>= 1) s += __shfl_xor_sync(0xffffffffu, s, o);
        if ((t & 31) == 0) ws[t >> 5] = s;
        __syncthreads();
        float tot = ws[0] + ws[1] + ws[2] + ws[3];
        float y = v / fmaxf(sqrtf(tot), 1e-12f);
        __nv_bfloat16 hi = __float2bfloat16(y);
        __nv_bfloat16 lo = __float2bfloat16(y - __bfloat162float(hi));
        if (isAu) {
            anh[(size_t)r * 128 + t] = hi;
            anl[(size_t)r * 128 + t] = lo;
        } else {
            snh[off + (size_t)r * 128 + t] = hi;
            snl[off + (size_t)r * 128 + t] = lo;
        }
    } else if (m < 45056) {
        int m2 = m - 18432;
        const float* X; const float* vec; float* y; int r; int mxi = -1;
        if (m2 < 12288) {
            int tpe = m2 >> 12;
            X = ha; vec = wdv + tpe * 128; y = ald + tpe * NA; r = m2 & 4095;
        } else {
            int m3 = m2 - 12288;
            if (m3 < 8192)       { X = gp; vec = gas;       y = alsp; r = m3;         mxi = 0; }
            else if (m3 < 12288) { X = gt; vec = gas + 128; y = alst; r = m3 - 8192;  mxi = 1; }
            else                 { X = gc; vec = gas + 256; y = alsc; r = m3 - 12288; mxi = 2; }
        }
        float s = X[(size_t)r * 128 + t] * vec[t];
        #pragma unroll
        for (int o = 16; o; o >>= 1) s += __shfl_xor_sync(0xffffffffu, s, o);
        if ((t & 31) == 0) ws[t >> 5] = s;
        __syncthreads();
        if (t == 0) {
            float tot = ws[0] + ws[1] + ws[2] + ws[3];
            y[r] = tot;
            if (mxi >= 0) atomicMax(&mxsEnc[mxi], enc_f(tot));
        }
    } else {
        int ti = m - 45056;
        const float* X; __nv_bfloat16* O; int Ns2, s0, d0;
        if (ti < 1024)      { X = gp; O = hsT;                          Ns2 = NP; s0 = (ti & 255) * 32; d0 = (ti >> 8) * 32; }
        else if (ti < 1536) { int u = ti - 1024; X = gt; O = hsT + (size_t)128 * NP;        Ns2 = NT; s0 = (u & 127) * 32; d0 = (u >> 7) * 32; }
        else                { int u = ti - 1536; X = gc; O = hsT + (size_t)128 * (NP + NT); Ns2 = NC; s0 = (u & 63) * 32;  d0 = (u >> 6) * 32; }
        int tx = t & 31, ty = t >> 5;
        #pragma unroll
        for (int r = 0; r < 8; r++) {
            int rr = r * 4 + ty;
            tile[rr][tx] = X[(size_t)(s0 + rr) * 128 + d0 + tx];
        }
        __syncthreads();
        #pragma unroll
        for (int r = 0; r < 8; r++) {
            int dd = r * 4 + ty;
            O[(size_t)(d0 + dd) * Ns2 + s0 + tx] = __float2bfloat16(tile[tx][dd]);
        }
    }
}

// ---------------- HMMA hetero GAT (R15: 256 thr, single-buffer cp.async, 2 CTA/SM) ----------------
#define HET_GRID 304
#define SA_ANH 0
#define SA_ANL 17408
#define SA_SNH 34816
#define SA_SNL 52224
#define SA_HST 69632
#define SA_W   88064
#define SA_ALD 97280
#define SA_ALS 97536
#define SA_TOT 97792

__global__ __launch_bounds__(256, 2) void hetero_mma(
    const __nv_bfloat16* __restrict__ anh, const __nv_bfloat16* __restrict__ anl,
    const float* __restrict__ ald3, const unsigned* __restrict__ mxsEnc,
    const __nv_bfloat16* __restrict__ snh, const __nv_bfloat16* __restrict__ snl,
    const __nv_bfloat16* __restrict__ hsT,
    const float* __restrict__ alsp, const float* __restrict__ alst,
    const float* __restrict__ alsc,
    float* __restrict__ acc, float* __restrict__ deng)
{
    extern __shared__ char sm[];
    unsigned sb = smem_u32(sm);
    float* sALD = (float*)(sm + SA_ALD);
    float* sALS = (float*)(sm + SA_ALS);

    int t = threadIdx.x, lane = t & 31, warp = t >> 5;
    int mt = warp >> 1, nh = warp & 1;
    int ltile = lane >> 3, lrow = lane & 7;
    int rowA = mt * 16 + ((ltile & 1) << 3) + lrow;
    unsigned colA = (unsigned)((ltile >> 1) * 16);
    int rowBl = ((ltile >> 1) << 3) + lrow;
    unsigned colB = (unsigned)((ltile & 1) * 16);
    int crow = lane >> 2;
    int ccol = (lane & 3) * 2;

    const int TOTC = 14336;
    int cs = (int)(((long long)blockIdx.x * TOTC) / HET_GRID);
    int ce = (int)(((long long)(blockIdx.x + 1) * TOTC) / HET_GRID);

    int curType = -1, curAb = -1, r0g = 0;
    const __nv_bfloat16 *snhT = snh, *snlT = snl, *hsTT = hsT;
    const float* alsT = alsp;
    int Ns = NP;
    float mx = 0.f, ald0 = 0.f, ald1 = 0.f, mrow0 = 0.f, mrow1 = 0.f;
    float den0 = 0.f, den1 = 0.f;
    float acc2[8][4];

    for (int c = cs; c < ce; c++) {
        int type, ab, ch;
        if (c < 8192)       { type = 0; ab = c >> 7; ch = c & 127; }
        else if (c < 12288) { int u = c - 8192;  type = 1; ab = u >> 6; ch = u & 63; }
        else                { int u = c - 12288; type = 2; ab = u >> 5; ch = u & 31; }
        int j0 = ch << 6;

        if (type != curType || ab != curAb) {
            if (curType >= 0) {
                int gr0 = r0g + mt * 16 + crow;
                #pragma unroll
                for (int nt = 0; nt < 8; nt++) {
                    int d = nh * 64 + nt * 8 + ccol;
                    float* b0 = acc + ((size_t)curType * NA + gr0) * 128 + d;
                    float* b1 = acc + ((size_t)curType * NA + gr0 + 8) * 128 + d;
                    atomicAdd(b0, acc2[nt][0]); atomicAdd(b0 + 1, acc2[nt][1]);
                    atomicAdd(b1, acc2[nt][2]); atomicAdd(b1 + 1, acc2[nt][3]);
                }
                float d0 = den0 + __shfl_xor_sync(0xffffffffu, den0, 1);
                d0 += __shfl_xor_sync(0xffffffffu, d0, 2);
                float d1 = den1 + __shfl_xor_sync(0xffffffffu, den1, 1);
                d1 += __shfl_xor_sync(0xffffffffu, d1, 2);
                if ((lane & 3) == 0) {
                    atomicAdd(deng + curType * NA + gr0, d0);
                    atomicAdd(deng + curType * NA + gr0 + 8, d1);
                }
            }
            curType = type; curAb = ab; r0g = ab << 6;
            if (type == 0)      { snhT = snh; snlT = snl; hsTT = hsT; alsT = alsp; Ns = NP; }
            else if (type == 1) { snhT = snh + (size_t)NP * 128; snlT = snl + (size_t)NP * 128;
                                  hsTT = hsT + (size_t)128 * NP; alsT = alst; Ns = NT; }
            else                { snhT = snh + (size_t)(NP + NT) * 128; snlT = snl + (size_t)(NP + NT) * 128;
                                  hsTT = hsT + (size_t)128 * (NP + NT); alsT = alsc; Ns = NC; }
            mx = dec_f(mxsEnc[type]);
            __syncthreads();
            for (int i = t; i < 1024; i += 256) {
                int r = i >> 4, q = i & 15;
                cp16(sb + SA_ANH + r * 272 + q * 16, anh + (size_t)(r0g + r) * 128 + q * 8);
                cp16(sb + SA_ANL + r * 272 + q * 16, anl + (size_t)(r0g + r) * 128 + q * 8);
            }
            if (t < 16) cp16(sb + SA_ALD + t * 16, ald3 + type * NA + r0g + t * 4);
            CP_WAIT();
            __syncthreads();
            ald0 = sALD[mt * 16 + crow];
            ald1 = sALD[mt * 16 + crow + 8];
            float tm0 = ald0 + mx; mrow0 = tm0 >= 0.f ? tm0 : 0.2f * tm0;
            float tm1 = ald1 + mx; mrow1 = tm1 >= 0.f ? tm1 : 0.2f * tm1;
            den0 = den1 = 0.f;
            #pragma unroll
            for (int nt = 0; nt < 8; nt++)
                #pragma unroll
                for (int p = 0; p < 4; p++) acc2[nt][p] = 0.f;
        }

        __syncthreads();
        for (int i = t; i < 1024; i += 256) {
            int r = i >> 4, q = i & 15;
            cp16(sb + SA_SNH + r * 272 + q * 16, snhT + (size_t)(j0 + r) * 128 + q * 8);
            cp16(sb + SA_SNL + r * 272 + q * 16, snlT + (size_t)(j0 + r) * 128 + q * 8);
            int hd = i >> 3, hq = i & 7;
            cp16(sb + SA_HST + hd * 144 + hq * 16, hsTT + (size_t)hd * Ns + j0 + hq * 8);
        }
        if (t < 16) cp16(sb + SA_ALS + t * 16, alsT + j0 + t * 4);
        CP_WAIT();
        __syncthreads();

        float acc1[4][4];
        #pragma unroll
        for (int nt = 0; nt < 4; nt++)
            #pragma unroll
            for (int p = 0; p < 4; p++) acc1[nt][p] = 0.f;
        #pragma unroll 1
        for (int pass = 0; pass < 3; pass++) {
            unsigned abase = sb + (pass < 2 ? SA_ANH : SA_ANL);
            unsigned bbase = sb + (pass == 1 ? SA_SNL : SA_SNH);
            #pragma unroll
            for (int k = 0; k < 8; k++) {
                unsigned a0, a1, a2, a3;
                ldsm4(abase + (unsigned)rowA * 272 + colA + k * 32, a0, a1, a2, a3);
                #pragma unroll
                for (int ntp = 0; ntp < 2; ntp++) {
                    unsigned b0, b1, b2, b3;
                    ldsm4(bbase + (unsigned)(nh * 32 + ntp * 16 + rowBl) * 272 + colB + k * 32,
                          b0, b1, b2, b3);
                    mma_bf16(acc1[ntp * 2],     a0, a1, a2, a3, b0, b1);
                    mma_bf16(acc1[ntp * 2 + 1], a0, a1, a2, a3, b2, b3);
                }
            }
        }

        int gr0 = r0g + mt * 16 + crow;
        #pragma unroll
        for (int nt = 0; nt < 4; nt++) {
            int jl = nh * 32 + nt * 8 + ccol;
            int jg = j0 + jl;
            float als0 = sALS[jl], als1 = sALS[jl + 1];
            float e0 = ald0 + als0; e0 = e0 >= 0.f ? e0 : 0.2f * e0;
            float e1 = ald0 + als1; e1 = e1 >= 0.f ? e1 : 0.2f * e1;
            float f0 = ald1 + als0; f0 = f0 >= 0.f ? f0 : 0.2f * f0;
            float f1 = ald1 + als1; f1 = f1 >= 0.f ? f1 : 0.2f * f1;
            float w00 = (acc1[nt][0] > 0.1f && gr0 != jg)         ? __expf(e0 - mrow0) : 0.f;
            float w01 = (acc1[nt][1] > 0.1f && gr0 != jg + 1)     ? __expf(e1 - mrow0) : 0.f;
            float w10 = (acc1[nt][2] > 0.1f && gr0 + 8 != jg)     ? __expf(f0 - mrow1) : 0.f;
            float w11 = (acc1[nt][3] > 0.1f && gr0 + 8 != jg + 1) ? __expf(f1 - mrow1) : 0.f;
            __nv_bfloat16 b00 = __float2bfloat16(w00), b01 = __float2bfloat16(w01);
            __nv_bfloat16 b10 = __float2bfloat16(w10), b11 = __float2bfloat16(w11);
            den0 += __bfloat162float(b00) + __bfloat162float(b01);
            den1 += __bfloat162float(b10) + __bfloat162float(b11);
            unsigned p0 = ((unsigned)__bfloat16_as_ushort(b01) << 16) | __bfloat16_as_ushort(b00);
            unsigned p1 = ((unsigned)__bfloat16_as_ushort(b11) << 16) | __bfloat16_as_ushort(b10);
            int r0l = mt * 16 + crow;
            *(unsigned*)(sm + SA_W + r0l * 144 + jl * 2) = p0;
            *(unsigned*)(sm + SA_W + (r0l + 8) * 144 + jl * 2) = p1;
        }
        __syncthreads();

        #pragma unroll
        for (int k = 0; k < 4; k++) {
            unsigned a0, a1, a2, a3;
            ldsm4(sb + SA_W + (unsigned)rowA * 144 + colA + k * 32, a0, a1, a2, a3);
            #pragma unroll
            for (int ntp = 0; ntp < 4; ntp++) {
                unsigned b0, b1, b2, b3;
                ldsm4(sb + SA_HST + (unsigned)(nh * 64 + ntp * 16 + rowBl) * 144 + colB + k * 32,
                      b0, b1, b2, b3);
                mma_bf16(acc2[ntp * 2],     a0, a1, a2, a3, b0, b1);
                mma_bf16(acc2[ntp * 2 + 1], a0, a1, a2, a3, b2, b3);
            }
        }
    }

    if (curType >= 0) {
        int gr0 = r0g + mt * 16 + crow;
        #pragma unroll
        for (int nt = 0; nt < 8; nt++) {
            int d = nh * 64 + nt * 8 + ccol;
            float* b0 = acc + ((size_t)curType * NA + gr0) * 128 + d;
            float* b1 = acc + ((size_t)curType * NA + gr0 + 8) * 128 + d;
            atomicAdd(b0, acc2[nt][0]); atomicAdd(b0 + 1, acc2[nt][1]);
            atomicAdd(b1, acc2[nt][2]); atomicAdd(b1 + 1, acc2[nt][3]);
        }
        float d0 = den0 + __shfl_xor_sync(0xffffffffu, den0, 1);
        d0 += __shfl_xor_sync(0xffffffffu, d0, 2);
        float d1 = den1 + __shfl_xor_sync(0xffffffffu, den1, 1);
        d1 += __shfl_xor_sync(0xffffffffu, d1, 2);
        if ((lane & 3) == 0) {
            atomicAdd(deng + curType * NA + gr0, d0);
            atomicAdd(deng + curType * NA + gr0 + 8, d1);
        }
    }
}

// attscore with fused finalize
__global__ void attscore_kernel(float* __restrict__ acc, const float* __restrict__ den,
                                const float* __restrict__ gb,
                                const float* __restrict__ xt,
                                const float* __restrict__ Watt, const float* __restrict__ atts,
                                float* __restrict__ ssum) {
    int set = blockIdx.y;
    int rb = blockIdx.x * 4, t = threadIdx.x, c = t & 63;
    __shared__ float xs[4][128];
    if (set < 3) {
        for (int i = t; i < 512; i += 256) {
            int rr = i >> 7, cc = i & 127;
            size_t idx = ((size_t)set * NA + rb + rr) * 128 + cc;
            float d = den[set * NA + rb + rr];
            float b = gb[set * 128 + cc];
            float v = (d > 0.f) ? acc[idx] / d + b : b;
            acc[idx] = v;
            xs[rr][cc] = v;
        }
    } else {
        for (int i = t; i < 512; i += 256)
            xs[i >> 7][i & 127] = xt[(size_t)(rb + (i >> 7)) * 128 + (i & 127)];
    }
    __syncthreads();
    const float* xr = xs[t >> 6];
    float dot = 0.f;
    #pragma unroll 8
    for (int k = 0; k < 128; k++) dot += xr[k] * Watt[k * 64 + c];
    float val = (1.f / (1.f + __expf(-dot))) * atts[set * 64 + c];
    #pragma unroll
    for (int o = 16; o; o >>= 1) val += __shfl_xor_sync(0xffffffffu, val, o);
    __shared__ float ps[8];
    if ((t & 31) == 0) ps[t >> 5] = val;
    __syncthreads();
    if (t == 0) {
        float s = 0.f;
        #pragma unroll
        for (int i = 0; i < 8; i++) s += ps[i];
        atomicAdd(&ssum[set], s);
    }
}

__global__ void alpha_kernel(const float* __restrict__ ssum, float* __restrict__ alpha) {
    if (threadIdx.x == 0) {
        float s[4], m = -3e38f;
        for (int i = 0; i < 4; i++) { s[i] = ssum[i] / (float)NA; m = fmaxf(m, s[i]); }
        float e[4], tot = 0.f;
        for (int i = 0; i < 4; i++) { e[i] = expf(s[i] - m); tot += e[i]; }
        for (int i = 0; i < 4; i++) alpha[i] = e[i] / tot;
    }
}

__global__ void xatt_kernel(const float* __restrict__ heter, const float* __restrict__ xt,
                            const float* __restrict__ alpha, float* __restrict__ out) {
    int idx = blockIdx.x * blockDim.x + threadIdx.x;
    if (idx >= NA * 128) return;
    out[idx] = alpha[0] * heter[idx] + alpha[1] * heter[NA * 128 + idx] +
               alpha[2] * heter[2 * NA * 128 + idx] + alpha[3] * xt[idx];
}

__global__ void degscatter_kernel(const float* __restrict__ X, const int* __restrict__ edge,
                                  float* __restrict__ deg, float* __restrict__ AGG, int E) {
    int idx = blockIdx.x * blockDim.x + threadIdx.x;
    if (idx < E) atomicAdd(&deg[edge[E + idx]], 1.0f);
    int sidx = idx - ((E + 255) & ~255);
    if (sidx < 0 || sidx >= E * 32) return;
    int e = sidx >> 5, q = sidx & 31;
    int s = edge[e], d = edge[E + e];
    float4 v = *(const float4*)&X[(size_t)s * 128 + q * 4];
    float* o = &AGG[(size_t)d * 128 + q * 4];
    atomicAdd(o + 0, v.x); atomicAdd(o + 1, v.y);
    atomicAdd(o + 2, v.z); atomicAdd(o + 3, v.w);
}

__global__ void scatter_kernel(const float* __restrict__ X, const int* __restrict__ src,
                               const int* __restrict__ dst, float* __restrict__ AGG,
                               int E, int C) {
    int idx = blockIdx.x * blockDim.x + threadIdx.x;
    int per = C >> 2;
    if (idx >= E * per) return;
    int e = idx / per, q = idx - e * per;
    int s = src[e], d = dst[e];
    float4 v = *(const float4*)&X[(size_t)s * C + q * 4];
    float* o = &AGG[(size_t)d * C + q * 4];
    atomicAdd(o + 0, v.x); atomicAdd(o + 1, v.y);
    atomicAdd(o + 2, v.z); atomicAdd(o + 3, v.w);
}

extern "C" void kernel_launch(void* const* d_in, const int* in_sizes, int n_in,
                              void* d_out, int out_size) {
    const float* x_ma = (const float*)d_in[0];
    const float* x_mp = (const float*)d_in[1];
    const float* x_mt = (const float*)d_in[2];
    const float* x_mc = (const float*)d_in[3];
    const float* x_ia = (const float*)d_in[4];
    const int*   edge = (const int*)d_in[5];
    const float* Wla  = (const float*)d_in[6];  const float* bla  = (const float*)d_in[7];
    const float* Wlp  = (const float*)d_in[8];  const float* blp  = (const float*)d_in[9];
    const float* Wlt  = (const float*)d_in[10]; const float* blt  = (const float*)d_in[11];
    const float* Wlc  = (const float*)d_in[12]; const float* blc  = (const float*)d_in[13];
    const float* Wltg = (const float*)d_in[14]; const float* bltg = (const float*)d_in[15];
    const float* gWs  = (const float*)d_in[16];
    const float* gWd  = (const float*)d_in[17];
    const float* gas  = (const float*)d_in[18];
    const float* gad  = (const float*)d_in[19];
    const float* gb   = (const float*)d_in[20];
    const float* Watt = (const float*)d_in[21];
    const float* atts = (const float*)d_in[22];
    const float* W1l  = (const float*)d_in[23]; const float* b1 = (const float*)d_in[24];
    const float* W1r  = (const float*)d_in[25];
    const float* W2l  = (const float*)d_in[26]; const float* b2 = (const float*)d_in[27];
    const float* W2r  = (const float*)d_in[28];

    int E = in_sizes[5] / 2;
    int Ka = in_sizes[0] / NA, Kp = in_sizes[1] / NP, Kt = in_sizes[2] / NT;
    int Kc = in_sizes[3] / NC, Kg = in_sizes[4] / NA;

    float* out_x   = (float*)d_out;
    float* out_att = (float*)d_out + (size_t)NA * 64;

    float *ha,*hp,*ht,*hc,*xt,*gp,*gt,*gc;
    float *alsp,*alst,*alsc,*ald,*wdv,*acc,*den,*ssum,*alpha,*agg1,*deg,*h1,*q,*aggq;
    unsigned* mxsEnc;
    __nv_bfloat16 *anh,*anl,*snh,*snl,*hsT,*wth,*wtl;
    cudaGetSymbolAddress((void**)&ha,g_ha);   cudaGetSymbolAddress((void**)&hp,g_hp);
    cudaGetSymbolAddress((void**)&ht,g_ht);   cudaGetSymbolAddress((void**)&hc,g_hc);
    cudaGetSymbolAddress((void**)&xt,g_xt);
    cudaGetSymbolAddress((void**)&anh,g_anh); cudaGetSymbolAddress((void**)&anl,g_anl);
    cudaGetSymbolAddress((void**)&snh,g_snh); cudaGetSymbolAddress((void**)&snl,g_snl);
    cudaGetSymbolAddress((void**)&hsT,g_hsT); cudaGetSymbolAddress((void**)&gp,g_gp);
    cudaGetSymbolAddress((void**)&gt,g_gt);   cudaGetSymbolAddress((void**)&gc,g_gc);
    cudaGetSymbolAddress((void**)&alsp,g_alsp); cudaGetSymbolAddress((void**)&alst,g_alst);
    cudaGetSymbolAddress((void**)&alsc,g_alsc); cudaGetSymbolAddress((void**)&ald,g_ald);
    cudaGetSymbolAddress((void**)&wdv,g_wdv);   cudaGetSymbolAddress((void**)&mxsEnc,g_mxsEnc);
    cudaGetSymbolAddress((void**)&acc,g_acc);   cudaGetSymbolAddress((void**)&den,g_den);
    cudaGetSymbolAddress((void**)&ssum,g_ssum); cudaGetSymbolAddress((void**)&alpha,g_alpha);
    cudaGetSymbolAddress((void**)&agg1,g_agg1); cudaGetSymbolAddress((void**)&deg,g_deg);
    cudaGetSymbolAddress((void**)&h1,g_h1);     cudaGetSymbolAddress((void**)&q,g_q);
    cudaGetSymbolAddress((void**)&aggq,g_aggq);
    cudaGetSymbolAddress((void**)&wth,g_wth);   cudaGetSymbolAddress((void**)&wtl,g_wtl);

    WJobs WP; int off = 0;
    auto wj = [&](const float* W, int K, int KP, int N, int slot) {
        WP.j[slot] = {W, K, KP, N, off}; off += KP * N;
    };
    wj(gWs + 0*16384, 128, 128, 128, 0);
    wj(gWs + 1*16384, 128, 128, 128, 1);
    wj(gWs + 2*16384, 128, 128, 128, 2);
    wj(W1l, 128, 128, 256, 3);  wj(W1r, 128, 128, 256, 4);
    wj(W2l, 256, 256, 64, 5);   wj(W2r, 256, 256, 64, 6);
    WP.total = off;
    WP.j[7] = {nullptr, 0, 1, 1, off};

    auto mj = [](const float*A, int woff, int K, int KP,
                 const float*A2, int woff2, int K2, int KP2,
                 const float*bias, const float*addD, const float*degp,
                 const float*degpA, float*C,
                 int M, int N, int relu, int colBlks, int blkStart) {
        MJob J; J.A=A; J.woff=woff; J.K=K; J.KP=KP;
        J.A2=A2; J.woff2=woff2; J.K2=K2; J.KP2=KP2;
        J.bias=bias; J.addD=addD; J.degp=degp; J.degpA=degpA; J.C=C;
        J.M=M; J.N=N; J.relu=relu; J.colBlks=colBlks; J.blkStart=blkStart;
        return J;
    };

    zero_wvec<<<2324,256>>>(acc, agg1, aggq, den, deg, ssum, mxsEnc, gWd, gad, wdv);
    wprep<<<(WP.total + 255) / 256, 256>>>(WP, wth, wtl);
    {
        LJobs B; B.n = 5;
        B.j[0] = {x_ma, Wla,  bla,  ha, Ka, 0};
        B.j[1] = {x_mp, Wlp,  blp,  hp, Kp, 64};
        B.j[2] = {x_mt, Wlt,  blt,  ht, Kt, 192};
        B.j[3] = {x_mc, Wlc,  blc,  hc, Kc, 256};
        B.j[4] = {x_ia, Wltg, bltg, xt, Kg, 288};
        lin_f32<<<352,256>>>(B);
    }
    {
        MJobs B; B.n = 3;
        B.j[0] = mj(hp, WP.j[0].off, 128, 128, 0,0,0,0, 0,0,0,0, gp, NP, 128, 0, 2, 0);
        B.j[1] = mj(ht, WP.j[1].off, 128, 128, 0,0,0,0, 0,0,0,0, gt, NT, 128, 0, 2, 256);
        B.j[2] = mj(hc, WP.j[2].off, 128, 128, 0,0,0,0, 0,0,0,0, gc, NC, 128, 0, 2, 384);
        lin_mma<<<448,256>>>(B, wth, wtl);
    }
    prep_all<<<46848,128>>>(ha, hp, ht, hc, anh, anl, snh, snl,
                            gp, gt, gc, wdv, gas, ald, alsp, alst, alsc, mxsEnc, hsT);
    cudaFuncSetAttribute(hetero_mma, cudaFuncAttributeMaxDynamicSharedMemorySize, SA_TOT);
    hetero_mma<<<HET_GRID,256,SA_TOT>>>(anh, anl, ald, mxsEnc, snh, snl, hsT,
                                        alsp, alst, alsc, acc, den);
    attscore_kernel<<<dim3(NA/4,4),256>>>(acc, den, gb, xt, Watt, atts, ssum);
    alpha_kernel<<<1,32>>>(ssum, alpha);
    xatt_kernel<<<(NA*128)/256,256>>>(acc, xt, alpha, out_att);
    {
        int degBlocks = (E + 255) / 256;
        int scatBlocks = (E * 32) / 256;
        degscatter_kernel<<<degBlocks + scatBlocks, 256>>>(ha, edge, deg, agg1, E);
    }
    {
        MJobs B; B.n = 1;
        B.j[0] = mj(agg1, WP.j[3].off, 128, 128, ha, WP.j[4].off, 128, 128,
                    b1, 0, 0, deg, h1, NA, 256, 1, 4, 0);
        lin_mma<<<256,256>>>(B, wth, wtl);
    }
    {
        MJobs B; B.n = 1;
        B.j[0] = mj(h1, WP.j[5].off, 256, 256, 0,0,0,0, 0,0,0,0, q, NA, 64, 0, 1, 0);
        lin_mma<<<64,256>>>(B, wth, wtl);
    }
    scatter_kernel<<<(E*16)/256,256>>>(q, edge, edge + E, aggq, E, 64);
    {
        MJobs B; B.n = 1;
        B.j[0] = mj(h1, WP.j[6].off, 256, 256, 0,0,0,0, b2, aggq, deg, 0, out_x, NA, 64, 0, 1, 0);
        lin_mma<<<64,256>>>(B, wth, wtl);
    }
}